// round 5
// baseline (speedup 1.0000x reference)
#include <cuda_runtime.h>
#include <cstdint>

#define WINDOW 512
#define S_LEN  4096
#define BH     16
#define TQ     128
#define TK     64
#define DD     64
#define NTH    256

// smem byte offsets (bf16 tiles, 128B rows, SW128 swizzle)
// Q: 128 rows x 128B (hi + lo) = 32KB
// K/V double-buffered: stage s at 32768 + s*32768, each stage {KH,KL,VH,VL} x 8KB
#define SM_QH 0
#define SM_QL 16384
#define SM_STAGE(s) (32768 + (s) * 32768)
#define OFF_KH 0
#define OFF_KL 8192
#define OFF_VH 16384
#define OFF_VL 24576
#define SM_TOTAL 98304

#define SWZ(x) ((x) ^ (((x) >> 3) & 0x70))

static __device__ __forceinline__ uint32_t s2u(const void* p) {
    uint32_t a;
    asm("{ .reg .u64 t; cvta.to.shared.u64 t, %1; cvt.u32.u64 %0, t; }" : "=r"(a) : "l"(p));
    return a;
}
static __device__ __forceinline__ float ex2f_(float x) {
    float y; asm("ex2.approx.f32 %0,%1;" : "=f"(y) : "f"(x)); return y;
}
// pack two floats as bf16x2: low half = first arg, high half = second arg
static __device__ __forceinline__ uint32_t packbf(float lo, float hi) {
    uint32_t r;
    asm("cvt.rn.bf16x2.f32 %0, %1, %2;" : "=r"(r) : "f"(hi), "f"(lo));
    return r;
}
// hi/lo bf16 split of a float pair
static __device__ __forceinline__ void split2(float a, float b, uint32_t& h, uint32_t& l) {
    h = packbf(a, b);
    float ra = a - __uint_as_float(h << 16);
    float rb = b - __uint_as_float(h & 0xFFFF0000u);
    l = packbf(ra, rb);
}

static __device__ __forceinline__ void ldsm4(uint32_t r[4], uint32_t addr) {
    asm volatile("ldmatrix.sync.aligned.m8n8.x4.shared.b16 {%0,%1,%2,%3}, [%4];"
                 : "=r"(r[0]), "=r"(r[1]), "=r"(r[2]), "=r"(r[3]) : "r"(addr));
}
static __device__ __forceinline__ void ldsm4t(uint32_t r[4], uint32_t addr) {
    asm volatile("ldmatrix.sync.aligned.m8n8.x4.trans.shared.b16 {%0,%1,%2,%3}, [%4];"
                 : "=r"(r[0]), "=r"(r[1]), "=r"(r[2]), "=r"(r[3]) : "r"(addr));
}
static __device__ __forceinline__ void mma16816(float c[4], const uint32_t a[4],
                                                uint32_t b0, uint32_t b1) {
    asm volatile(
        "mma.sync.aligned.m16n8k16.row.col.f32.bf16.bf16.f32 "
        "{%0,%1,%2,%3}, {%4,%5,%6,%7}, {%8,%9}, {%0,%1,%2,%3};"
        : "+f"(c[0]), "+f"(c[1]), "+f"(c[2]), "+f"(c[3])
        : "r"(a[0]), "r"(a[1]), "r"(a[2]), "r"(a[3]), "r"(b0), "r"(b1));
}

// split 16 floats (4x float4) to bf16 hi/lo and store 2x16B to each tile
static __device__ __forceinline__ void splitstore(const float4 f[4], char* sH, char* sL,
                                                  int rel, float scale) {
    uint32_t h[8], l[8];
    #pragma unroll
    for (int i = 0; i < 4; i++) {
        split2(f[i].x * scale, f[i].y * scale, h[2 * i],     l[2 * i]);
        split2(f[i].z * scale, f[i].w * scale, h[2 * i + 1], l[2 * i + 1]);
    }
    *(uint4*)(sH + SWZ(rel))      = make_uint4(h[0], h[1], h[2], h[3]);
    *(uint4*)(sH + SWZ(rel + 16)) = make_uint4(h[4], h[5], h[6], h[7]);
    *(uint4*)(sL + SWZ(rel))      = make_uint4(l[0], l[1], l[2], l[3]);
    *(uint4*)(sL + SWZ(rel + 16)) = make_uint4(l[4], l[5], l[6], l[7]);
}

extern __shared__ __align__(1024) char smem[];

__global__ void __launch_bounds__(NTH)
swa_mma_kernel(const float* __restrict__ Qp,
               const float* __restrict__ Kp,
               const float* __restrict__ Vp,
               float* __restrict__ Op) {
    const int tid  = threadIdx.x;
    const int lane = tid & 31;
    const int warp = tid >> 5;
    const int bh   = blockIdx.y;
    const int q0   = blockIdx.x * TQ;
    const size_t base = (size_t)bh * S_LEN * DD;
    const uint32_t sb = s2u(smem);

    const int trow = tid >> 2, q4 = tid & 3;   // staging coords: row 0..63, quarter

    // ---- stage Q (128x64) into smem as hi/lo bf16, pre-scaled to log2 domain ----
    {
        const float qs = 0.125f * 1.44269504088896340736f;
        #pragma unroll
        for (int half = 0; half < 2; half++) {
            const int row = trow + half * 64;
            const float4* g = (const float4*)(Qp + base + (size_t)(q0 + row) * DD + q4 * 16);
            float4 f[4];
            #pragma unroll
            for (int i = 0; i < 4; i++) f[i] = g[i];
            splitstore(f, smem + SM_QH, smem + SM_QL, row * 128 + q4 * 32, qs);
        }
    }

    // per-lane fragment address components
    const int g_   = lane >> 2;
    const int tig  = lane & 3;
    const int rowA = (warp << 4) + (lane & 15);
    const int cA16 = (lane >> 4) * 16;
    const int rkK  = (lane & 7) + ((lane >> 4) & 1) * 8;
    const int cK16 = ((lane >> 3) & 1) * 16;
    const int rkV  = (lane & 7) + ((lane >> 3) & 1) * 8;
    const int cV16 = ((lane >> 4) & 1) * 16;

    float o[8][4];
    #pragma unroll
    for (int i = 0; i < 8; i++)
        #pragma unroll
        for (int e = 0; e < 4; e++) o[i][e] = 0.0f;
    float l0 = 0.0f, l1 = 0.0f;

    const int qmin = q0 + (warp << 4);
    const int qmax = qmin + 15;
    const int kt0 = (q0 >= WINDOW - 1) ? ((q0 - WINDOW + 1) >> 6) : 0;
    const int kt1 = (q0 + TQ - 1) >> 6;

    // ---- prologue: load + stage tile kt0 into buffer 0 ----
    {
        const float4* kg = (const float4*)(Kp + base + (size_t)(kt0 * TK + trow) * DD + q4 * 16);
        const float4* vg = (const float4*)(Vp + base + (size_t)(kt0 * TK + trow) * DD + q4 * 16);
        float4 kf[4], vf[4];
        #pragma unroll
        for (int i = 0; i < 4; i++) { kf[i] = kg[i]; vf[i] = vg[i]; }
        char* st = smem + SM_STAGE(0);
        splitstore(kf, st + OFF_KH, st + OFF_KL, trow * 128 + q4 * 32, 1.0f);
        splitstore(vf, st + OFF_VH, st + OFF_VL, trow * 128 + q4 * 32, 1.0f);
    }
    __syncthreads();

    for (int kt = kt0; kt <= kt1; kt++) {
        const int stage = (kt - kt0) & 1;
        const uint32_t sbase = sb + SM_STAGE(stage);

        // issue next tile's global loads FIRST (latency hidden under compute)
        float4 kf[4], vf[4];
        const bool more = (kt < kt1);
        if (more) {
            const float4* kg = (const float4*)(Kp + base + (size_t)((kt + 1) * TK + trow) * DD + q4 * 16);
            const float4* vg = (const float4*)(Vp + base + (size_t)((kt + 1) * TK + trow) * DD + q4 * 16);
            #pragma unroll
            for (int i = 0; i < 4; i++) { kf[i] = kg[i]; vf[i] = vg[i]; }
        }

        // per-warp window skip (uniform across warp)
        const bool active = !(kt * TK > qmax || kt * TK + (TK - 1) < qmin - (WINDOW - 1));
        if (active) {
            // ---- QK^T: S = (Qh+Ql)(Kh+Kl)^T, 3 combos ----
            float s[8][4];
            #pragma unroll
            for (int i = 0; i < 8; i++)
                #pragma unroll
                for (int e = 0; e < 4; e++) s[i][e] = 0.0f;

            #pragma unroll
            for (int kc = 0; kc < 4; kc++) {
                uint32_t aqh[4], aql[4];
                ldsm4(aqh, sb + SM_QH + SWZ(rowA * 128 + kc * 32 + cA16));
                ldsm4(aql, sb + SM_QL + SWZ(rowA * 128 + kc * 32 + cA16));
                #pragma unroll
                for (int pr = 0; pr < 4; pr++) {
                    const uint32_t off = SWZ((pr * 16 + rkK) * 128 + kc * 32 + cK16);
                    uint32_t bh_[4], bl_[4];
                    ldsm4(bh_, sbase + OFF_KH + off);
                    ldsm4(bl_, sbase + OFF_KL + off);
                    mma16816(s[2 * pr],     aqh, bh_[0], bh_[1]);
                    mma16816(s[2 * pr + 1], aqh, bh_[2], bh_[3]);
                    mma16816(s[2 * pr],     aqh, bl_[0], bl_[1]);
                    mma16816(s[2 * pr + 1], aqh, bl_[2], bl_[3]);
                    mma16816(s[2 * pr],     aql, bh_[0], bh_[1]);
                    mma16816(s[2 * pr + 1], aql, bh_[2], bh_[3]);
                }
            }

            // ---- softmax numerator + repack into PV A-fragments ----
            uint32_t pah[4][4], pal[4][4];
            const int qr0 = q0 + (warp << 4) + g_;
            const int qr1 = qr0 + 8;
            const int jb  = kt * TK;
            #pragma unroll
            for (int nb = 0; nb < 8; nb++) {
                const int j0 = jb + nb * 8 + 2 * tig;
                const int j1 = j0 + 1;
                float p0 = (j0 <= qr0 && j0 + (WINDOW - 1) >= qr0) ? ex2f_(s[nb][0]) : 0.0f;
                float p1 = (j1 <= qr0 && j1 + (WINDOW - 1) >= qr0) ? ex2f_(s[nb][1]) : 0.0f;
                float p2 = (j0 <= qr1 && j0 + (WINDOW - 1) >= qr1) ? ex2f_(s[nb][2]) : 0.0f;
                float p3 = (j1 <= qr1 && j1 + (WINDOW - 1) >= qr1) ? ex2f_(s[nb][3]) : 0.0f;
                l0 += p0 + p1;
                l1 += p2 + p3;
                uint32_t h01, lo01, h23, lo23;
                split2(p0, p1, h01, lo01);
                split2(p2, p3, h23, lo23);
                const int kc2 = nb >> 1, sub = nb & 1;
                pah[kc2][sub * 2]     = h01;
                pah[kc2][sub * 2 + 1] = h23;
                pal[kc2][sub * 2]     = lo01;
                pal[kc2][sub * 2 + 1] = lo23;
            }

            // ---- PV: O += (Ph+Pl)(Vh+Vl), 3 combos ----
            #pragma unroll
            for (int kc2 = 0; kc2 < 4; kc2++) {
                #pragma unroll
                for (int pr = 0; pr < 4; pr++) {
                    const uint32_t off = SWZ((kc2 * 16 + rkV) * 128 + pr * 32 + cV16);
                    uint32_t vh_[4], vl_[4];
                    ldsm4t(vh_, sbase + OFF_VH + off);
                    ldsm4t(vl_, sbase + OFF_VL + off);
                    mma16816(o[2 * pr],     pah[kc2], vh_[0], vh_[1]);
                    mma16816(o[2 * pr + 1], pah[kc2], vh_[2], vh_[3]);
                    mma16816(o[2 * pr],     pah[kc2], vl_[0], vl_[1]);
                    mma16816(o[2 * pr + 1], pah[kc2], vl_[2], vl_[3]);
                    mma16816(o[2 * pr],     pal[kc2], vh_[0], vh_[1]);
                    mma16816(o[2 * pr + 1], pal[kc2], vh_[2], vh_[3]);
                }
            }
        }

        // ---- stage next tile into the other buffer ----
        if (more) {
            char* st = smem + SM_STAGE(stage ^ 1);
            splitstore(kf, st + OFF_KH, st + OFF_KL, trow * 128 + q4 * 32, 1.0f);
            splitstore(vf, st + OFF_VH, st + OFF_VL, trow * 128 + q4 * 32, 1.0f);
        }
        __syncthreads();
    }

    // ---- finalize: row sums across the 4 lanes of each group, normalize, store ----
    l0 += __shfl_xor_sync(0xffffffffu, l0, 1);
    l0 += __shfl_xor_sync(0xffffffffu, l0, 2);
    l1 += __shfl_xor_sync(0xffffffffu, l1, 1);
    l1 += __shfl_xor_sync(0xffffffffu, l1, 2);
    const float inv0 = 1.0f / l0;
    const float inv1 = 1.0f / l1;

    const int r0 = q0 + (warp << 4) + g_;
    const int r1 = r0 + 8;
    float* orow0 = Op + base + (size_t)r0 * DD;
    float* orow1 = Op + base + (size_t)r1 * DD;
    #pragma unroll
    for (int nb = 0; nb < 8; nb++) {
        const int c = nb * 8 + 2 * tig;
        *(float2*)(orow0 + c) = make_float2(o[nb][0] * inv0, o[nb][1] * inv0);
        *(float2*)(orow1 + c) = make_float2(o[nb][2] * inv1, o[nb][3] * inv1);
    }
}

extern "C" void kernel_launch(void* const* d_in, const int* in_sizes, int n_in,
                              void* d_out, int out_size) {
    const float* Q = (const float*)d_in[0];
    const float* K = (const float*)d_in[1];
    const float* V = (const float*)d_in[2];
    float* O = (float*)d_out;
    (void)in_sizes; (void)n_in; (void)out_size;

    cudaFuncSetAttribute(swa_mma_kernel, cudaFuncAttributeMaxDynamicSharedMemorySize, SM_TOTAL);
    dim3 grid(S_LEN / TQ, BH);   // (32, 16) = 512 blocks
    swa_mma_kernel<<<grid, NTH, SM_TOTAL>>>(Q, K, V, O);
}

// round 9
// speedup vs baseline: 1.1423x; 1.1423x over previous
#include <cuda_runtime.h>
#include <cstdint>

#define WINDOW 512
#define S_LEN  4096
#define BH     16
#define TQ     128
#define TK     64
#define DD     64
#define NTH    256

// smem byte offsets (bf16 tiles, 128B rows, SW128 swizzle). 64KB total/CTA.
#define SM_QH 0
#define SM_QL 16384
#define SM_KH 32768
#define SM_KL 40960
#define SM_VH 49152
#define SM_VL 57344
#define SM_TOTAL 65536

#define SWZ(x) ((x) ^ (((x) >> 3) & 0x70))

static __device__ __forceinline__ uint32_t s2u(const void* p) {
    uint32_t a;
    asm("{ .reg .u64 t; cvta.to.shared.u64 t, %1; cvt.u32.u64 %0, t; }" : "=r"(a) : "l"(p));
    return a;
}
static __device__ __forceinline__ float ex2f_(float x) {
    float y; asm("ex2.approx.f32 %0,%1;" : "=f"(y) : "f"(x)); return y;
}
// pack two floats as bf16x2: low half = first arg, high half = second arg
static __device__ __forceinline__ uint32_t packbf(float lo, float hi) {
    uint32_t r;
    asm("cvt.rn.bf16x2.f32 %0, %1, %2;" : "=r"(r) : "f"(hi), "f"(lo));
    return r;
}
// hi/lo bf16 split of a float pair
static __device__ __forceinline__ void split2(float a, float b, uint32_t& h, uint32_t& l) {
    h = packbf(a, b);
    float ra = a - __uint_as_float(h << 16);
    float rb = b - __uint_as_float(h & 0xFFFF0000u);
    l = packbf(ra, rb);
}

static __device__ __forceinline__ void ldsm4(uint32_t r[4], uint32_t addr) {
    asm volatile("ldmatrix.sync.aligned.m8n8.x4.shared.b16 {%0,%1,%2,%3}, [%4];"
                 : "=r"(r[0]), "=r"(r[1]), "=r"(r[2]), "=r"(r[3]) : "r"(addr));
}
static __device__ __forceinline__ void ldsm4t(uint32_t r[4], uint32_t addr) {
    asm volatile("ldmatrix.sync.aligned.m8n8.x4.trans.shared.b16 {%0,%1,%2,%3}, [%4];"
                 : "=r"(r[0]), "=r"(r[1]), "=r"(r[2]), "=r"(r[3]) : "r"(addr));
}
static __device__ __forceinline__ void mma16816(float c[4], const uint32_t a[4],
                                                uint32_t b0, uint32_t b1) {
    asm volatile(
        "mma.sync.aligned.m16n8k16.row.col.f32.bf16.bf16.f32 "
        "{%0,%1,%2,%3}, {%4,%5,%6,%7}, {%8,%9}, {%0,%1,%2,%3};"
        : "+f"(c[0]), "+f"(c[1]), "+f"(c[2]), "+f"(c[3])
        : "r"(a[0]), "r"(a[1]), "r"(a[2]), "r"(a[3]), "r"(b0), "r"(b1));
}

// read 16 consecutive floats, scale, split to bf16 hi/lo, store 2x16B each
static __device__ __forceinline__ void store16split(const float4* g, char* sH, char* sL,
                                                   int rel, float scale) {
    float4 f[4];
    #pragma unroll
    for (int i = 0; i < 4; i++) f[i] = g[i];
    uint32_t h[8], l[8];
    #pragma unroll
    for (int i = 0; i < 4; i++) {
        split2(f[i].x * scale, f[i].y * scale, h[2 * i],     l[2 * i]);
        split2(f[i].z * scale, f[i].w * scale, h[2 * i + 1], l[2 * i + 1]);
    }
    *(uint4*)(sH + SWZ(rel))      = make_uint4(h[0], h[1], h[2], h[3]);
    *(uint4*)(sH + SWZ(rel + 16)) = make_uint4(h[4], h[5], h[6], h[7]);
    *(uint4*)(sL + SWZ(rel))      = make_uint4(l[0], l[1], l[2], l[3]);
    *(uint4*)(sL + SWZ(rel + 16)) = make_uint4(l[4], l[5], l[6], l[7]);
}

extern __shared__ __align__(1024) char smem[];

__global__ void __launch_bounds__(NTH, 2)
swa_mma_kernel(const float* __restrict__ Qp,
               const float* __restrict__ Kp,
               const float* __restrict__ Vp,
               float* __restrict__ Op) {
    const int tid  = threadIdx.x;
    const int lane = tid & 31;
    const int warp = tid >> 5;
    const int bh   = blockIdx.y;
    const int q0   = blockIdx.x * TQ;
    const size_t base = (size_t)bh * S_LEN * DD;
    const uint32_t sb = s2u(smem);

    const int trow = tid >> 2, q4 = tid & 3;   // staging coords

    // ---- stage Q (128x64) into smem as hi/lo bf16, pre-scaled to log2 domain ----
    {
        const float qs = 0.125f * 1.44269504088896340736f;
        #pragma unroll
        for (int half = 0; half < 2; half++) {
            const int row = trow + half * 64;
            const float4* g = (const float4*)(Qp + base + (size_t)(q0 + row) * DD + q4 * 16);
            store16split(g, smem + SM_QH, smem + SM_QL, row * 128 + q4 * 32, qs);
        }
    }

    // per-lane fragment address components
    const int g_   = lane >> 2;
    const int tig  = lane & 3;
    const int rowA = (warp << 4) + (lane & 15);
    const int cA16 = (lane >> 4) * 16;
    const int rkK  = (lane & 7) + ((lane >> 4) & 1) * 8;
    const int cK16 = ((lane >> 3) & 1) * 16;
    const int rkV  = (lane & 7) + ((lane >> 3) & 1) * 8;
    const int cV16 = ((lane >> 4) & 1) * 16;

    float o[8][4];
    #pragma unroll
    for (int i = 0; i < 8; i++)
        #pragma unroll
        for (int e = 0; e < 4; e++) o[i][e] = 0.0f;
    float l0 = 0.0f, l1 = 0.0f;

    const int qmin = q0 + (warp << 4);
    const int qmax = qmin + 15;
    const int kt0 = (q0 >= WINDOW - 1) ? ((q0 - WINDOW + 1) >> 6) : 0;
    const int kt1 = (q0 + TQ - 1) >> 6;

    for (int kt = kt0; kt <= kt1; kt++) {
        __syncthreads();   // previous tile fully consumed
        // ---- cooperative K/V tile load + bf16 split (single buffer) ----
        {
            const float4* kg = (const float4*)(Kp + base + (size_t)(kt * TK + trow) * DD + q4 * 16);
            store16split(kg, smem + SM_KH, smem + SM_KL, trow * 128 + q4 * 32, 1.0f);
            const float4* vg = (const float4*)(Vp + base + (size_t)(kt * TK + trow) * DD + q4 * 16);
            store16split(vg, smem + SM_VH, smem + SM_VL, trow * 128 + q4 * 32, 1.0f);
        }
        __syncthreads();

        // per-warp window skip (uniform across warp)
        const int jb = kt * TK;
        if (jb > qmax || jb + (TK - 1) < qmin - (WINDOW - 1)) continue;
        // tile fully inside every lane's window? (skip masking)
        const bool fullv = (jb + (TK - 1) <= qmin) && (jb >= qmax - (WINDOW - 1));

        const int qr0 = qmin + g_;
        const int qr1 = qr0 + 8;

        uint32_t pah[4][4], pal[4][4];

        // ---- QK^T streamed in two n32-halves: only 16 score regs live ----
        #pragma unroll
        for (int h = 0; h < 2; h++) {
            float s[4][4];
            #pragma unroll
            for (int i = 0; i < 4; i++)
                #pragma unroll
                for (int e = 0; e < 4; e++) s[i][e] = 0.0f;

            #pragma unroll
            for (int kc = 0; kc < 4; kc++) {
                uint32_t aqh[4], aql[4];
                ldsm4(aqh, sb + SM_QH + SWZ(rowA * 128 + kc * 32 + cA16));
                ldsm4(aql, sb + SM_QL + SWZ(rowA * 128 + kc * 32 + cA16));
                #pragma unroll
                for (int b = 0; b < 2; b++) {
                    const int pr = 2 * h + b;
                    const uint32_t off = SWZ((pr * 16 + rkK) * 128 + kc * 32 + cK16);
                    uint32_t bh_[4], bl_[4];
                    ldsm4(bh_, sb + SM_KH + off);
                    ldsm4(bl_, sb + SM_KL + off);
                    mma16816(s[2 * b],     aqh, bh_[0], bh_[1]);
                    mma16816(s[2 * b + 1], aqh, bh_[2], bh_[3]);
                    mma16816(s[2 * b],     aqh, bl_[0], bl_[1]);
                    mma16816(s[2 * b + 1], aqh, bl_[2], bl_[3]);
                    mma16816(s[2 * b],     aql, bh_[0], bh_[1]);
                    mma16816(s[2 * b + 1], aql, bh_[2], bh_[3]);
                }
            }

            // ---- softmax numerator + repack this half into PV A-fragments ----
            #pragma unroll
            for (int ln = 0; ln < 4; ln++) {
                const int nb = 4 * h + ln;
                float p0, p1, p2, p3;
                if (fullv) {
                    p0 = ex2f_(s[ln][0]);
                    p1 = ex2f_(s[ln][1]);
                    p2 = ex2f_(s[ln][2]);
                    p3 = ex2f_(s[ln][3]);
                } else {
                    const int j0 = jb + nb * 8 + 2 * tig;
                    const int j1 = j0 + 1;
                    p0 = (j0 <= qr0 && j0 + (WINDOW - 1) >= qr0) ? ex2f_(s[ln][0]) : 0.0f;
                    p1 = (j1 <= qr0 && j1 + (WINDOW - 1) >= qr0) ? ex2f_(s[ln][1]) : 0.0f;
                    p2 = (j0 <= qr1 && j0 + (WINDOW - 1) >= qr1) ? ex2f_(s[ln][2]) : 0.0f;
                    p3 = (j1 <= qr1 && j1 + (WINDOW - 1) >= qr1) ? ex2f_(s[ln][3]) : 0.0f;
                }
                l0 += p0 + p1;
                l1 += p2 + p3;
                uint32_t h01, lo01, h23, lo23;
                split2(p0, p1, h01, lo01);
                split2(p2, p3, h23, lo23);
                const int kc2 = 2 * h + (ln >> 1), sub = ln & 1;
                pah[kc2][sub * 2]     = h01;
                pah[kc2][sub * 2 + 1] = h23;
                pal[kc2][sub * 2]     = lo01;
                pal[kc2][sub * 2 + 1] = lo23;
            }
        }

        // ---- PV: O += (Ph+Pl)(Vh+Vl), 3 combos ----
        #pragma unroll
        for (int kc2 = 0; kc2 < 4; kc2++) {
            #pragma unroll
            for (int pr = 0; pr < 4; pr++) {
                const uint32_t off = SWZ((kc2 * 16 + rkV) * 128 + pr * 32 + cV16);
                uint32_t vh_[4], vl_[4];
                ldsm4t(vh_, sb + SM_VH + off);
                ldsm4t(vl_, sb + SM_VL + off);
                mma16816(o[2 * pr],     pah[kc2], vh_[0], vh_[1]);
                mma16816(o[2 * pr + 1], pah[kc2], vh_[2], vh_[3]);
                mma16816(o[2 * pr],     pah[kc2], vl_[0], vl_[1]);
                mma16816(o[2 * pr + 1], pah[kc2], vl_[2], vl_[3]);
                mma16816(o[2 * pr],     pal[kc2], vh_[0], vh_[1]);
                mma16816(o[2 * pr + 1], pal[kc2], vh_[2], vh_[3]);
            }
        }
    }

    // ---- finalize: row sums across the 4 lanes of each group, normalize, store ----
    l0 += __shfl_xor_sync(0xffffffffu, l0, 1);
    l0 += __shfl_xor_sync(0xffffffffu, l0, 2);
    l1 += __shfl_xor_sync(0xffffffffu, l1, 1);
    l1 += __shfl_xor_sync(0xffffffffu, l1, 2);
    const float inv0 = 1.0f / l0;
    const float inv1 = 1.0f / l1;

    const int r0 = q0 + (warp << 4) + g_;
    const int r1 = r0 + 8;
    float* orow0 = Op + base + (size_t)r0 * DD;
    float* orow1 = Op + base + (size_t)r1 * DD;
    #pragma unroll
    for (int nb = 0; nb < 8; nb++) {
        const int c = nb * 8 + 2 * tig;
        *(float2*)(orow0 + c) = make_float2(o[nb][0] * inv0, o[nb][1] * inv0);
        *(float2*)(orow1 + c) = make_float2(o[nb][2] * inv1, o[nb][3] * inv1);
    }
}

extern "C" void kernel_launch(void* const* d_in, const int* in_sizes, int n_in,
                              void* d_out, int out_size) {
    const float* Q = (const float*)d_in[0];
    const float* K = (const float*)d_in[1];
    const float* V = (const float*)d_in[2];
    float* O = (float*)d_out;
    (void)in_sizes; (void)n_in; (void)out_size;

    cudaFuncSetAttribute(swa_mma_kernel, cudaFuncAttributeMaxDynamicSharedMemorySize, SM_TOTAL);
    dim3 grid(S_LEN / TQ, BH);   // (32, 16) = 512 blocks
    swa_mma_kernel<<<grid, NTH, SM_TOTAL>>>(Q, K, V, O);
}

// round 10
// speedup vs baseline: 1.3712x; 1.2004x over previous
#include <cuda_runtime.h>
#include <cuda_fp16.h>
#include <cstdint>

#define WINDOW 512
#define S_LEN  4096
#define BH     16
#define TQ     128
#define TK     64
#define DD     64
#define NTH    256

// smem byte offsets (fp16 tiles, 128B rows, SW128 swizzle). 48KB total/CTA.
#define SM_QH 0
#define SM_QL 16384
#define SM_K  32768
#define SM_V  40960
#define SM_TOTAL 49152

#define SWZ(x) ((x) ^ (((x) >> 3) & 0x70))

static __device__ __forceinline__ uint32_t s2u(const void* p) {
    uint32_t a;
    asm("{ .reg .u64 t; cvta.to.shared.u64 t, %1; cvt.u32.u64 %0, t; }" : "=r"(a) : "l"(p));
    return a;
}
static __device__ __forceinline__ float ex2f_(float x) {
    float y; asm("ex2.approx.f32 %0,%1;" : "=f"(y) : "f"(x)); return y;
}
// pack two floats as f16x2: low half = first arg
static __device__ __forceinline__ uint32_t pack2h(float a, float b) {
    uint32_t r;
    asm("cvt.rn.f16x2.f32 %0, %1, %2;" : "=r"(r) : "f"(b), "f"(a));
    return r;
}
// fp16 hi/lo split of a float pair
static __device__ __forceinline__ void split2h(float a, float b, uint32_t& h, uint32_t& l) {
    __half ha = __float2half_rn(a), hb = __float2half_rn(b);
    float ra = a - __half2float(ha);
    float rb = b - __half2float(hb);
    h = ((uint32_t)__half_as_ushort(hb) << 16) | (uint32_t)__half_as_ushort(ha);
    l = pack2h(ra, rb);
}

static __device__ __forceinline__ void ldsm4(uint32_t r[4], uint32_t addr) {
    asm volatile("ldmatrix.sync.aligned.m8n8.x4.shared.b16 {%0,%1,%2,%3}, [%4];"
                 : "=r"(r[0]), "=r"(r[1]), "=r"(r[2]), "=r"(r[3]) : "r"(addr));
}
static __device__ __forceinline__ void ldsm4t(uint32_t r[4], uint32_t addr) {
    asm volatile("ldmatrix.sync.aligned.m8n8.x4.trans.shared.b16 {%0,%1,%2,%3}, [%4];"
                 : "=r"(r[0]), "=r"(r[1]), "=r"(r[2]), "=r"(r[3]) : "r"(addr));
}
static __device__ __forceinline__ void mma16816(float c[4], const uint32_t a[4],
                                                uint32_t b0, uint32_t b1) {
    asm volatile(
        "mma.sync.aligned.m16n8k16.row.col.f32.f16.f16.f32 "
        "{%0,%1,%2,%3}, {%4,%5,%6,%7}, {%8,%9}, {%0,%1,%2,%3};"
        : "+f"(c[0]), "+f"(c[1]), "+f"(c[2]), "+f"(c[3])
        : "r"(a[0]), "r"(a[1]), "r"(a[2]), "r"(a[3]), "r"(b0), "r"(b1));
}

// 16 floats -> fp16 single tile (16B x2)
static __device__ __forceinline__ void store16h(const float4* g, char* s, int rel) {
    float4 f[4];
    #pragma unroll
    for (int i = 0; i < 4; i++) f[i] = g[i];
    uint32_t w[8];
    #pragma unroll
    for (int i = 0; i < 4; i++) {
        w[2 * i]     = pack2h(f[i].x, f[i].y);
        w[2 * i + 1] = pack2h(f[i].z, f[i].w);
    }
    *(uint4*)(s + SWZ(rel))      = make_uint4(w[0], w[1], w[2], w[3]);
    *(uint4*)(s + SWZ(rel + 16)) = make_uint4(w[4], w[5], w[6], w[7]);
}
// 16 floats -> fp16 hi/lo split tiles
static __device__ __forceinline__ void store16sp(const float4* g, char* sH, char* sL,
                                                 int rel, float scale) {
    float4 f[4];
    #pragma unroll
    for (int i = 0; i < 4; i++) f[i] = g[i];
    uint32_t h[8], l[8];
    #pragma unroll
    for (int i = 0; i < 4; i++) {
        split2h(f[i].x * scale, f[i].y * scale, h[2 * i],     l[2 * i]);
        split2h(f[i].z * scale, f[i].w * scale, h[2 * i + 1], l[2 * i + 1]);
    }
    *(uint4*)(sH + SWZ(rel))      = make_uint4(h[0], h[1], h[2], h[3]);
    *(uint4*)(sH + SWZ(rel + 16)) = make_uint4(h[4], h[5], h[6], h[7]);
    *(uint4*)(sL + SWZ(rel))      = make_uint4(l[0], l[1], l[2], l[3]);
    *(uint4*)(sL + SWZ(rel + 16)) = make_uint4(l[4], l[5], l[6], l[7]);
}

extern __shared__ __align__(1024) char smem[];

__global__ void __launch_bounds__(NTH, 2)
swa_mma_kernel(const float* __restrict__ Qp,
               const float* __restrict__ Kp,
               const float* __restrict__ Vp,
               float* __restrict__ Op) {
    const int tid  = threadIdx.x;
    const int lane = tid & 31;
    const int warp = tid >> 5;
    const int bh   = blockIdx.y;
    const int q0   = blockIdx.x * TQ;
    const size_t base = (size_t)bh * S_LEN * DD;
    const uint32_t sb = s2u(smem);

    const int trow = tid >> 2, q4 = tid & 3;   // staging coords

    // ---- stage Q (128x64) as fp16 hi/lo, pre-scaled to log2 domain ----
    {
        const float qs = 0.125f * 1.44269504088896340736f;
        #pragma unroll
        for (int half = 0; half < 2; half++) {
            const int row = trow + half * 64;
            const float4* g = (const float4*)(Qp + base + (size_t)(q0 + row) * DD + q4 * 16);
            store16sp(g, smem + SM_QH, smem + SM_QL, row * 128 + q4 * 32, qs);
        }
    }
    __syncthreads();

    // per-lane fragment address components
    const int g_   = lane >> 2;
    const int tig  = lane & 3;
    const int rowA = (warp << 4) + (lane & 15);
    const int cA16 = (lane >> 4) * 16;
    const int rkK  = (lane & 7) + ((lane >> 4) & 1) * 8;
    const int cK16 = ((lane >> 3) & 1) * 16;
    const int rkV  = (lane & 7) + ((lane >> 3) & 1) * 8;
    const int cV16 = ((lane >> 4) & 1) * 16;

    // ---- Q fragments resident in registers for the whole kt loop ----
    uint32_t aqh[4][4], aql[4][4];
    #pragma unroll
    for (int kc = 0; kc < 4; kc++) {
        ldsm4(aqh[kc], sb + SM_QH + SWZ(rowA * 128 + kc * 32 + cA16));
        ldsm4(aql[kc], sb + SM_QL + SWZ(rowA * 128 + kc * 32 + cA16));
    }

    float o[8][4];
    #pragma unroll
    for (int i = 0; i < 8; i++)
        #pragma unroll
        for (int e = 0; e < 4; e++) o[i][e] = 0.0f;
    float l0 = 0.0f, l1 = 0.0f;

    const int qmin = q0 + (warp << 4);
    const int qmax = qmin + 15;
    const int kt0 = (q0 >= WINDOW - 1) ? ((q0 - WINDOW + 1) >> 6) : 0;
    const int kt1 = (q0 + TQ - 1) >> 6;

    for (int kt = kt0; kt <= kt1; kt++) {
        __syncthreads();   // previous tile fully consumed
        // ---- cooperative K/V tile load (single fp16 tiles) ----
        {
            const float4* kg = (const float4*)(Kp + base + (size_t)(kt * TK + trow) * DD + q4 * 16);
            store16h(kg, smem + SM_K, trow * 128 + q4 * 32);
            const float4* vg = (const float4*)(Vp + base + (size_t)(kt * TK + trow) * DD + q4 * 16);
            store16h(vg, smem + SM_V, trow * 128 + q4 * 32);
        }
        __syncthreads();

        // per-warp window skip (uniform across warp)
        const int jb = kt * TK;
        if (jb > qmax || jb + (TK - 1) < qmin - (WINDOW - 1)) continue;
        const bool fullv = (jb + (TK - 1) <= qmin) && (jb >= qmax - (WINDOW - 1));

        const int qr0 = qmin + g_;
        const int qr1 = qr0 + 8;

        // ---- two n32-halves; each: QK -> softmax -> PV (P never in smem) ----
        #pragma unroll
        for (int h = 0; h < 2; h++) {
            float s[4][4];
            #pragma unroll
            for (int i = 0; i < 4; i++)
                #pragma unroll
                for (int e = 0; e < 4; e++) s[i][e] = 0.0f;

            #pragma unroll
            for (int kc = 0; kc < 4; kc++) {
                uint32_t kb0[4], kb1[4];
                ldsm4(kb0, sb + SM_K + SWZ(((2 * h)     * 16 + rkK) * 128 + kc * 32 + cK16));
                ldsm4(kb1, sb + SM_K + SWZ(((2 * h + 1) * 16 + rkK) * 128 + kc * 32 + cK16));
                // round-robin over 4 accumulators: dep distance 4
                mma16816(s[0], aqh[kc], kb0[0], kb0[1]);
                mma16816(s[1], aqh[kc], kb0[2], kb0[3]);
                mma16816(s[2], aqh[kc], kb1[0], kb1[1]);
                mma16816(s[3], aqh[kc], kb1[2], kb1[3]);
                mma16816(s[0], aql[kc], kb0[0], kb0[1]);
                mma16816(s[1], aql[kc], kb0[2], kb0[3]);
                mma16816(s[2], aql[kc], kb1[0], kb1[1]);
                mma16816(s[3], aql[kc], kb1[2], kb1[3]);
            }

            // ---- softmax numerator + repack into PV A-fragments (fp16 split) ----
            uint32_t pah[2][4], pal[2][4];
            #pragma unroll
            for (int ln = 0; ln < 4; ln++) {
                const int nb = 4 * h + ln;
                float p0, p1, p2, p3;
                if (fullv) {
                    p0 = ex2f_(s[ln][0]);
                    p1 = ex2f_(s[ln][1]);
                    p2 = ex2f_(s[ln][2]);
                    p3 = ex2f_(s[ln][3]);
                } else {
                    const int j0 = jb + nb * 8 + 2 * tig;
                    const int j1 = j0 + 1;
                    p0 = (j0 <= qr0 && j0 + (WINDOW - 1) >= qr0) ? ex2f_(s[ln][0]) : 0.0f;
                    p1 = (j1 <= qr0 && j1 + (WINDOW - 1) >= qr0) ? ex2f_(s[ln][1]) : 0.0f;
                    p2 = (j0 <= qr1 && j0 + (WINDOW - 1) >= qr1) ? ex2f_(s[ln][2]) : 0.0f;
                    p3 = (j1 <= qr1 && j1 + (WINDOW - 1) >= qr1) ? ex2f_(s[ln][3]) : 0.0f;
                }
                l0 += p0 + p1;
                l1 += p2 + p3;
                uint32_t h01, lo01, h23, lo23;
                split2h(p0, p1, h01, lo01);
                split2h(p2, p3, h23, lo23);
                const int c = ln >> 1, sub = ln & 1;
                pah[c][sub * 2]     = h01;
                pah[c][sub * 2 + 1] = h23;
                pal[c][sub * 2]     = lo01;
                pal[c][sub * 2 + 1] = lo23;
            }

            // ---- PV for this half's two key chunks: O += (Ph+Pl)*V ----
            #pragma unroll
            for (int c = 0; c < 2; c++) {
                const int kc2 = 2 * h + c;
                #pragma unroll
                for (int pr = 0; pr < 4; pr++) {
                    uint32_t vb[4];
                    ldsm4t(vb, sb + SM_V + SWZ((kc2 * 16 + rkV) * 128 + pr * 32 + cV16));
                    mma16816(o[2 * pr],     pah[c], vb[0], vb[1]);
                    mma16816(o[2 * pr + 1], pah[c], vb[2], vb[3]);
                    mma16816(o[2 * pr],     pal[c], vb[0], vb[1]);
                    mma16816(o[2 * pr + 1], pal[c], vb[2], vb[3]);
                }
            }
        }
    }

    // ---- finalize: row sums across the 4 lanes of each group, normalize, store ----
    l0 += __shfl_xor_sync(0xffffffffu, l0, 1);
    l0 += __shfl_xor_sync(0xffffffffu, l0, 2);
    l1 += __shfl_xor_sync(0xffffffffu, l1, 1);
    l1 += __shfl_xor_sync(0xffffffffu, l1, 2);
    const float inv0 = 1.0f / l0;
    const float inv1 = 1.0f / l1;

    const int r0 = q0 + (warp << 4) + g_;
    const int r1 = r0 + 8;
    float* orow0 = Op + base + (size_t)r0 * DD;
    float* orow1 = Op + base + (size_t)r1 * DD;
    #pragma unroll
    for (int nb = 0; nb < 8; nb++) {
        const int c = nb * 8 + 2 * tig;
        *(float2*)(orow0 + c) = make_float2(o[nb][0] * inv0, o[nb][1] * inv0);
        *(float2*)(orow1 + c) = make_float2(o[nb][2] * inv1, o[nb][3] * inv1);
    }
}

extern "C" void kernel_launch(void* const* d_in, const int* in_sizes, int n_in,
                              void* d_out, int out_size) {
    const float* Q = (const float*)d_in[0];
    const float* K = (const float*)d_in[1];
    const float* V = (const float*)d_in[2];
    float* O = (float*)d_out;
    (void)in_sizes; (void)n_in; (void)out_size;

    cudaFuncSetAttribute(swa_mma_kernel, cudaFuncAttributeMaxDynamicSharedMemorySize, SM_TOTAL);
    dim3 grid(S_LEN / TQ, BH);   // (32, 16) = 512 blocks
    swa_mma_kernel<<<grid, NTH, SM_TOTAL>>>(Q, K, V, O);
}

// round 11
// speedup vs baseline: 1.6703x; 1.2181x over previous
#include <cuda_runtime.h>
#include <cuda_fp16.h>
#include <cstdint>

#define WINDOW 512
#define S_LEN  4096
#define BH     16
#define TQ     128
#define TK     64
#define DD     64
#define NTH    256

// smem: Q hi/lo (32KB) + 2-stage K/V fp16 ring (2 x 16KB) = 64KB/CTA
#define SM_QH 0
#define SM_QL 16384
#define SM_STG(s) (32768 + (s) * 16384)
#define OFF_K 0
#define OFF_V 8192
#define SM_TOTAL 65536

#define SWZ(x) ((x) ^ (((x) >> 3) & 0x70))

// fp16 K/V scratch: 16 * 4096 * 64 halves = 8MB each
#define KV_CHUNKS (BH * S_LEN * DD / 8)
__device__ uint4 g_kh[KV_CHUNKS];
__device__ uint4 g_vh[KV_CHUNKS];

static __device__ __forceinline__ uint32_t s2u(const void* p) {
    uint32_t a;
    asm("{ .reg .u64 t; cvta.to.shared.u64 t, %1; cvt.u32.u64 %0, t; }" : "=r"(a) : "l"(p));
    return a;
}
static __device__ __forceinline__ float ex2f_(float x) {
    float y; asm("ex2.approx.f32 %0,%1;" : "=f"(y) : "f"(x)); return y;
}
static __device__ __forceinline__ uint32_t pack2h(float a, float b) {
    uint32_t r;
    asm("cvt.rn.f16x2.f32 %0, %1, %2;" : "=r"(r) : "f"(b), "f"(a));
    return r;
}
static __device__ __forceinline__ void split2h(float a, float b, uint32_t& h, uint32_t& l) {
    __half ha = __float2half_rn(a), hb = __float2half_rn(b);
    float ra = a - __half2float(ha);
    float rb = b - __half2float(hb);
    h = ((uint32_t)__half_as_ushort(hb) << 16) | (uint32_t)__half_as_ushort(ha);
    l = pack2h(ra, rb);
}

static __device__ __forceinline__ void ldsm4(uint32_t r[4], uint32_t addr) {
    asm volatile("ldmatrix.sync.aligned.m8n8.x4.shared.b16 {%0,%1,%2,%3}, [%4];"
                 : "=r"(r[0]), "=r"(r[1]), "=r"(r[2]), "=r"(r[3]) : "r"(addr));
}
static __device__ __forceinline__ void ldsm4t(uint32_t r[4], uint32_t addr) {
    asm volatile("ldmatrix.sync.aligned.m8n8.x4.trans.shared.b16 {%0,%1,%2,%3}, [%4];"
                 : "=r"(r[0]), "=r"(r[1]), "=r"(r[2]), "=r"(r[3]) : "r"(addr));
}
static __device__ __forceinline__ void mma16816(float c[4], const uint32_t a[4],
                                                uint32_t b0, uint32_t b1) {
    asm volatile(
        "mma.sync.aligned.m16n8k16.row.col.f32.f16.f16.f32 "
        "{%0,%1,%2,%3}, {%4,%5,%6,%7}, {%8,%9}, {%0,%1,%2,%3};"
        : "+f"(c[0]), "+f"(c[1]), "+f"(c[2]), "+f"(c[3])
        : "r"(a[0]), "r"(a[1]), "r"(a[2]), "r"(a[3]), "r"(b0), "r"(b1));
}
static __device__ __forceinline__ void cpasync16(uint32_t sdst, const void* gsrc) {
    asm volatile("cp.async.cg.shared.global [%0], [%1], 16;"
                 :: "r"(sdst), "l"(gsrc) : "memory");
}

// fp32 -> fp16 hi/lo split of 16 floats into two smem tiles
static __device__ __forceinline__ void store16sp(const float4* g, char* sH, char* sL,
                                                 int rel, float scale) {
    float4 f[4];
    #pragma unroll
    for (int i = 0; i < 4; i++) f[i] = g[i];
    uint32_t h[8], l[8];
    #pragma unroll
    for (int i = 0; i < 4; i++) {
        split2h(f[i].x * scale, f[i].y * scale, h[2 * i],     l[2 * i]);
        split2h(f[i].z * scale, f[i].w * scale, h[2 * i + 1], l[2 * i + 1]);
    }
    *(uint4*)(sH + SWZ(rel))      = make_uint4(h[0], h[1], h[2], h[3]);
    *(uint4*)(sH + SWZ(rel + 16)) = make_uint4(h[4], h[5], h[6], h[7]);
    *(uint4*)(sL + SWZ(rel))      = make_uint4(l[0], l[1], l[2], l[3]);
    *(uint4*)(sL + SWZ(rel + 16)) = make_uint4(l[4], l[5], l[6], l[7]);
}

// ---- prepass: convert K,V fp32 -> fp16 scratch ----
__global__ void __launch_bounds__(512)
cvt_kv_kernel(const float* __restrict__ Kp, const float* __restrict__ Vp) {
    const int i = blockIdx.x * 512 + threadIdx.x;   // one uint4 (8 halves) each
    if (i >= KV_CHUNKS) return;
    const float4* ks = (const float4*)(Kp + (size_t)i * 8);
    const float4* vs = (const float4*)(Vp + (size_t)i * 8);
    float4 a = ks[0], b = ks[1];
    g_kh[i] = make_uint4(pack2h(a.x, a.y), pack2h(a.z, a.w),
                         pack2h(b.x, b.y), pack2h(b.z, b.w));
    a = vs[0]; b = vs[1];
    g_vh[i] = make_uint4(pack2h(a.x, a.y), pack2h(a.z, a.w),
                         pack2h(b.x, b.y), pack2h(b.z, b.w));
}

extern __shared__ __align__(1024) char smem[];

__global__ void __launch_bounds__(NTH, 2)
swa_mma_kernel(const float* __restrict__ Qp, float* __restrict__ Op) {
    const int tid  = threadIdx.x;
    const int lane = tid & 31;
    const int warp = tid >> 5;
    const int bh   = blockIdx.y;
    const int q0   = blockIdx.x * TQ;
    const size_t base = (size_t)bh * S_LEN * DD;
    const uint32_t sb = s2u(smem);

    // staging coords for cp.async: row 0..63, two 16B chunks per thread per tensor
    const int srow = tid >> 2;
    const int sc0  = (tid & 3) * 32;            // byte offset of first chunk pair
    const char* gk = (const char*)g_kh + (size_t)bh * S_LEN * 128;
    const char* gv = (const char*)g_vh + (size_t)bh * S_LEN * 128;

    const int kt0 = (q0 >= WINDOW - 1) ? ((q0 - WINDOW + 1) >> 6) : 0;
    const int kt1 = (q0 + TQ - 1) >> 6;

    // ---- prologue: async-load tile kt0 into stage 0 ----
    {
        const char* ks = gk + (size_t)(kt0 * TK + srow) * 128 + sc0;
        const char* vs = gv + (size_t)(kt0 * TK + srow) * 128 + sc0;
        const uint32_t d = sb + SM_STG(0) + 0;
        cpasync16(d + OFF_K + SWZ(srow * 128 + sc0),      ks);
        cpasync16(d + OFF_K + SWZ(srow * 128 + sc0 + 16), ks + 16);
        cpasync16(d + OFF_V + SWZ(srow * 128 + sc0),      vs);
        cpasync16(d + OFF_V + SWZ(srow * 128 + sc0 + 16), vs + 16);
        asm volatile("cp.async.commit_group;" ::: "memory");
    }

    // ---- stage Q (128x64) as fp16 hi/lo, pre-scaled to log2 domain ----
    {
        const float qs = 0.125f * 1.44269504088896340736f;
        const int trow = tid >> 2, q4 = tid & 3;
        #pragma unroll
        for (int half = 0; half < 2; half++) {
            const int row = trow + half * 64;
            const float4* g = (const float4*)(Qp + base + (size_t)(q0 + row) * DD + q4 * 16);
            store16sp(g, smem + SM_QH, smem + SM_QL, row * 128 + q4 * 32, qs);
        }
    }
    __syncthreads();

    // per-lane fragment address components
    const int g_   = lane >> 2;
    const int tig  = lane & 3;
    const int rowA = (warp << 4) + (lane & 15);
    const int cA16 = (lane >> 4) * 16;
    const int rkK  = (lane & 7) + ((lane >> 4) & 1) * 8;
    const int cK16 = ((lane >> 3) & 1) * 16;
    const int rkV  = (lane & 7) + ((lane >> 3) & 1) * 8;
    const int cV16 = ((lane >> 4) & 1) * 16;

    // ---- Q fragments resident in registers for the whole kt loop ----
    uint32_t aqh[4][4], aql[4][4];
    #pragma unroll
    for (int kc = 0; kc < 4; kc++) {
        ldsm4(aqh[kc], sb + SM_QH + SWZ(rowA * 128 + kc * 32 + cA16));
        ldsm4(aql[kc], sb + SM_QL + SWZ(rowA * 128 + kc * 32 + cA16));
    }

    float o[8][4];
    #pragma unroll
    for (int i = 0; i < 8; i++)
        #pragma unroll
        for (int e = 0; e < 4; e++) o[i][e] = 0.0f;
    float l0 = 0.0f, l1 = 0.0f;

    const int qmin = q0 + (warp << 4);
    const int qmax = qmin + 15;

    for (int kt = kt0; kt <= kt1; kt++) {
        // tile kt's async group is the only one pending -> wait for arrival
        asm volatile("cp.async.wait_group 0;" ::: "memory");
        __syncthreads();   // all warps past compute(kt-1); buf kt visible

        // overlap: issue async load of tile kt+1 into the other stage
        if (kt < kt1) {
            const char* ks = gk + (size_t)((kt + 1) * TK + srow) * 128 + sc0;
            const char* vs = gv + (size_t)((kt + 1) * TK + srow) * 128 + sc0;
            const uint32_t d = sb + SM_STG((kt + 1 - kt0) & 1);
            cpasync16(d + OFF_K + SWZ(srow * 128 + sc0),      ks);
            cpasync16(d + OFF_K + SWZ(srow * 128 + sc0 + 16), ks + 16);
            cpasync16(d + OFF_V + SWZ(srow * 128 + sc0),      vs);
            cpasync16(d + OFF_V + SWZ(srow * 128 + sc0 + 16), vs + 16);
            asm volatile("cp.async.commit_group;" ::: "memory");
        }

        // per-warp window skip (uniform across warp)
        const int jb = kt * TK;
        if (jb > qmax || jb + (TK - 1) < qmin - (WINDOW - 1)) continue;
        const bool fullv = (jb + (TK - 1) <= qmin) && (jb >= qmax - (WINDOW - 1));

        const uint32_t sk = sb + SM_STG((kt - kt0) & 1) + OFF_K;
        const uint32_t sv = sb + SM_STG((kt - kt0) & 1) + OFF_V;
        const int qr0 = qmin + g_;
        const int qr1 = qr0 + 8;

        // ---- two n32-halves; each: QK -> softmax -> PV (P never in smem) ----
        #pragma unroll
        for (int h = 0; h < 2; h++) {
            float s[4][4];
            #pragma unroll
            for (int i = 0; i < 4; i++)
                #pragma unroll
                for (int e = 0; e < 4; e++) s[i][e] = 0.0f;

            #pragma unroll
            for (int kc = 0; kc < 4; kc++) {
                uint32_t kb0[4], kb1[4];
                ldsm4(kb0, sk + SWZ(((2 * h)     * 16 + rkK) * 128 + kc * 32 + cK16));
                ldsm4(kb1, sk + SWZ(((2 * h + 1) * 16 + rkK) * 128 + kc * 32 + cK16));
                mma16816(s[0], aqh[kc], kb0[0], kb0[1]);
                mma16816(s[1], aqh[kc], kb0[2], kb0[3]);
                mma16816(s[2], aqh[kc], kb1[0], kb1[1]);
                mma16816(s[3], aqh[kc], kb1[2], kb1[3]);
                mma16816(s[0], aql[kc], kb0[0], kb0[1]);
                mma16816(s[1], aql[kc], kb0[2], kb0[3]);
                mma16816(s[2], aql[kc], kb1[0], kb1[1]);
                mma16816(s[3], aql[kc], kb1[2], kb1[3]);
            }

            // ---- softmax numerator + repack into PV A-fragments ----
            uint32_t pah[2][4], pal[2][4];
            #pragma unroll
            for (int ln = 0; ln < 4; ln++) {
                const int nb = 4 * h + ln;
                float p0, p1, p2, p3;
                if (fullv) {
                    p0 = ex2f_(s[ln][0]);
                    p1 = ex2f_(s[ln][1]);
                    p2 = ex2f_(s[ln][2]);
                    p3 = ex2f_(s[ln][3]);
                } else {
                    const int j0 = jb + nb * 8 + 2 * tig;
                    const int j1 = j0 + 1;
                    p0 = (j0 <= qr0 && j0 + (WINDOW - 1) >= qr0) ? ex2f_(s[ln][0]) : 0.0f;
                    p1 = (j1 <= qr0 && j1 + (WINDOW - 1) >= qr0) ? ex2f_(s[ln][1]) : 0.0f;
                    p2 = (j0 <= qr1 && j0 + (WINDOW - 1) >= qr1) ? ex2f_(s[ln][2]) : 0.0f;
                    p3 = (j1 <= qr1 && j1 + (WINDOW - 1) >= qr1) ? ex2f_(s[ln][3]) : 0.0f;
                }
                l0 += p0 + p1;
                l1 += p2 + p3;
                uint32_t h01, lo01, h23, lo23;
                split2h(p0, p1, h01, lo01);
                split2h(p2, p3, h23, lo23);
                const int c = ln >> 1, sub = ln & 1;
                pah[c][sub * 2]     = h01;
                pah[c][sub * 2 + 1] = h23;
                pal[c][sub * 2]     = lo01;
                pal[c][sub * 2 + 1] = lo23;
            }

            // ---- PV for this half's two key chunks ----
            #pragma unroll
            for (int c = 0; c < 2; c++) {
                const int kc2 = 2 * h + c;
                #pragma unroll
                for (int pr = 0; pr < 4; pr++) {
                    uint32_t vb[4];
                    ldsm4t(vb, sv + SWZ((kc2 * 16 + rkV) * 128 + pr * 32 + cV16));
                    mma16816(o[2 * pr],     pah[c], vb[0], vb[1]);
                    mma16816(o[2 * pr + 1], pah[c], vb[2], vb[3]);
                    mma16816(o[2 * pr],     pal[c], vb[0], vb[1]);
                    mma16816(o[2 * pr + 1], pal[c], vb[2], vb[3]);
                }
            }
        }
    }

    // ---- finalize ----
    l0 += __shfl_xor_sync(0xffffffffu, l0, 1);
    l0 += __shfl_xor_sync(0xffffffffu, l0, 2);
    l1 += __shfl_xor_sync(0xffffffffu, l1, 1);
    l1 += __shfl_xor_sync(0xffffffffu, l1, 2);
    const float inv0 = 1.0f / l0;
    const float inv1 = 1.0f / l1;

    const int r0 = q0 + (warp << 4) + g_;
    const int r1 = r0 + 8;
    float* orow0 = Op + base + (size_t)r0 * DD;
    float* orow1 = Op + base + (size_t)r1 * DD;
    #pragma unroll
    for (int nb = 0; nb < 8; nb++) {
        const int c = nb * 8 + 2 * tig;
        *(float2*)(orow0 + c) = make_float2(o[nb][0] * inv0, o[nb][1] * inv0);
        *(float2*)(orow1 + c) = make_float2(o[nb][2] * inv1, o[nb][3] * inv1);
    }
}

extern "C" void kernel_launch(void* const* d_in, const int* in_sizes, int n_in,
                              void* d_out, int out_size) {
    const float* Q = (const float*)d_in[0];
    const float* K = (const float*)d_in[1];
    const float* V = (const float*)d_in[2];
    float* O = (float*)d_out;
    (void)in_sizes; (void)n_in; (void)out_size;

    cvt_kv_kernel<<<(KV_CHUNKS + 511) / 512, 512>>>(K, V);

    cudaFuncSetAttribute(swa_mma_kernel, cudaFuncAttributeMaxDynamicSharedMemorySize, SM_TOTAL);
    dim3 grid(S_LEN / TQ, BH);   // (32, 16) = 512 blocks
    swa_mma_kernel<<<grid, NTH, SM_TOTAL>>>(Q, O);
}

// round 12
// speedup vs baseline: 2.0142x; 1.2059x over previous
#include <cuda_runtime.h>
#include <cuda_fp16.h>
#include <cstdint>

#define WINDOW 512
#define S_LEN  4096
#define BH     16
#define TQ     128
#define TK     64
#define DD     64
#define NTH    256

// smem: Q fp16 (16KB) + 2-stage K/V fp16 ring (2 x 16KB) = 48KB/CTA
#define SM_Q  0
#define SM_STG(s) (16384 + (s) * 16384)
#define OFF_K 0
#define OFF_V 8192
#define SM_TOTAL 49152

#define SWZ(x) ((x) ^ (((x) >> 3) & 0x70))

// fp16 K/V scratch: 16 * 4096 * 64 halves = 8MB each
#define KV_CHUNKS (BH * S_LEN * DD / 8)
__device__ uint4 g_kh[KV_CHUNKS];
__device__ uint4 g_vh[KV_CHUNKS];

static __device__ __forceinline__ uint32_t s2u(const void* p) {
    uint32_t a;
    asm("{ .reg .u64 t; cvta.to.shared.u64 t, %1; cvt.u32.u64 %0, t; }" : "=r"(a) : "l"(p));
    return a;
}
static __device__ __forceinline__ float ex2f_(float x) {
    float y; asm("ex2.approx.f32 %0,%1;" : "=f"(y) : "f"(x)); return y;
}
static __device__ __forceinline__ uint32_t pack2h(float a, float b) {
    uint32_t r;
    asm("cvt.rn.f16x2.f32 %0, %1, %2;" : "=r"(r) : "f"(b), "f"(a));
    return r;
}

static __device__ __forceinline__ void ldsm4(uint32_t r[4], uint32_t addr) {
    asm volatile("ldmatrix.sync.aligned.m8n8.x4.shared.b16 {%0,%1,%2,%3}, [%4];"
                 : "=r"(r[0]), "=r"(r[1]), "=r"(r[2]), "=r"(r[3]) : "r"(addr));
}
static __device__ __forceinline__ void ldsm4t(uint32_t r[4], uint32_t addr) {
    asm volatile("ldmatrix.sync.aligned.m8n8.x4.trans.shared.b16 {%0,%1,%2,%3}, [%4];"
                 : "=r"(r[0]), "=r"(r[1]), "=r"(r[2]), "=r"(r[3]) : "r"(addr));
}
static __device__ __forceinline__ void mma16816(float c[4], const uint32_t a[4],
                                                uint32_t b0, uint32_t b1) {
    asm volatile(
        "mma.sync.aligned.m16n8k16.row.col.f32.f16.f16.f32 "
        "{%0,%1,%2,%3}, {%4,%5,%6,%7}, {%8,%9}, {%0,%1,%2,%3};"
        : "+f"(c[0]), "+f"(c[1]), "+f"(c[2]), "+f"(c[3])
        : "r"(a[0]), "r"(a[1]), "r"(a[2]), "r"(a[3]), "r"(b0), "r"(b1));
}
static __device__ __forceinline__ void cpasync16(uint32_t sdst, const void* gsrc) {
    asm volatile("cp.async.cg.shared.global [%0], [%1], 16;"
                 :: "r"(sdst), "l"(gsrc) : "memory");
}

// 16 floats -> scaled fp16 tile (two 16B stores)
static __device__ __forceinline__ void store16h(const float4* g, char* s, int rel, float scale) {
    float4 f[4];
    #pragma unroll
    for (int i = 0; i < 4; i++) f[i] = g[i];
    uint32_t w[8];
    #pragma unroll
    for (int i = 0; i < 4; i++) {
        w[2 * i]     = pack2h(f[i].x * scale, f[i].y * scale);
        w[2 * i + 1] = pack2h(f[i].z * scale, f[i].w * scale);
    }
    *(uint4*)(s + SWZ(rel))      = make_uint4(w[0], w[1], w[2], w[3]);
    *(uint4*)(s + SWZ(rel + 16)) = make_uint4(w[4], w[5], w[6], w[7]);
}

// ---- prepass: convert K,V fp32 -> fp16 scratch ----
__global__ void __launch_bounds__(512)
cvt_kv_kernel(const float* __restrict__ Kp, const float* __restrict__ Vp) {
    const int i = blockIdx.x * 512 + threadIdx.x;   // one uint4 (8 halves) each
    if (i >= KV_CHUNKS) return;
    const float4* ks = (const float4*)(Kp + (size_t)i * 8);
    const float4* vs = (const float4*)(Vp + (size_t)i * 8);
    float4 a = ks[0], b = ks[1];
    g_kh[i] = make_uint4(pack2h(a.x, a.y), pack2h(a.z, a.w),
                         pack2h(b.x, b.y), pack2h(b.z, b.w));
    a = vs[0]; b = vs[1];
    g_vh[i] = make_uint4(pack2h(a.x, a.y), pack2h(a.z, a.w),
                         pack2h(b.x, b.y), pack2h(b.z, b.w));
}

extern __shared__ __align__(1024) char smem[];

__global__ void __launch_bounds__(NTH, 2)
swa_mma_kernel(const float* __restrict__ Qp, float* __restrict__ Op) {
    const int tid  = threadIdx.x;
    const int lane = tid & 31;
    const int warp = tid >> 5;
    const int bh   = blockIdx.y;
    const int q0   = blockIdx.x * TQ;
    const size_t base = (size_t)bh * S_LEN * DD;
    const uint32_t sb = s2u(smem);

    // staging coords for cp.async: row 0..63, two 16B chunks per thread per tensor
    const int srow = tid >> 2;
    const int sc0  = (tid & 3) * 32;
    const char* gk = (const char*)g_kh + (size_t)bh * S_LEN * 128;
    const char* gv = (const char*)g_vh + (size_t)bh * S_LEN * 128;

    const int kt0 = (q0 >= WINDOW - 1) ? ((q0 - WINDOW + 1) >> 6) : 0;
    const int kt1 = (q0 + TQ - 1) >> 6;

    // ---- prologue: async-load tile kt0 into stage 0 ----
    {
        const char* ks = gk + (size_t)(kt0 * TK + srow) * 128 + sc0;
        const char* vs = gv + (size_t)(kt0 * TK + srow) * 128 + sc0;
        const uint32_t d = sb + SM_STG(0);
        cpasync16(d + OFF_K + SWZ(srow * 128 + sc0),      ks);
        cpasync16(d + OFF_K + SWZ(srow * 128 + sc0 + 16), ks + 16);
        cpasync16(d + OFF_V + SWZ(srow * 128 + sc0),      vs);
        cpasync16(d + OFF_V + SWZ(srow * 128 + sc0 + 16), vs + 16);
        asm volatile("cp.async.commit_group;" ::: "memory");
    }

    // ---- stage Q (128x64) as fp16, pre-scaled to log2 domain ----
    {
        const float qs = 0.125f * 1.44269504088896340736f;
        const int trow = tid >> 2, q4 = tid & 3;
        #pragma unroll
        for (int half = 0; half < 2; half++) {
            const int row = trow + half * 64;
            const float4* g = (const float4*)(Qp + base + (size_t)(q0 + row) * DD + q4 * 16);
            store16h(g, smem + SM_Q, row * 128 + q4 * 32, qs);
        }
    }
    __syncthreads();

    // per-lane fragment address components
    const int g_   = lane >> 2;
    const int tig  = lane & 3;
    const int rowA = (warp << 4) + (lane & 15);
    const int cA16 = (lane >> 4) * 16;
    const int rkK  = (lane & 7) + ((lane >> 4) & 1) * 8;
    const int cK16 = ((lane >> 3) & 1) * 16;
    const int rkV  = (lane & 7) + ((lane >> 3) & 1) * 8;
    const int cV16 = ((lane >> 4) & 1) * 16;

    // ---- Q fragments resident in registers for the whole kt loop ----
    uint32_t aq[4][4];
    #pragma unroll
    for (int kc = 0; kc < 4; kc++)
        ldsm4(aq[kc], sb + SM_Q + SWZ(rowA * 128 + kc * 32 + cA16));

    float o[8][4];
    #pragma unroll
    for (int i = 0; i < 8; i++)
        #pragma unroll
        for (int e = 0; e < 4; e++) o[i][e] = 0.0f;
    float l0 = 0.0f, l1 = 0.0f;

    const int qmin = q0 + (warp << 4);
    const int qmax = qmin + 15;

    for (int kt = kt0; kt <= kt1; kt++) {
        asm volatile("cp.async.wait_group 0;" ::: "memory");
        __syncthreads();

        // overlap: issue async load of tile kt+1 into the other stage
        if (kt < kt1) {
            const char* ks = gk + (size_t)((kt + 1) * TK + srow) * 128 + sc0;
            const char* vs = gv + (size_t)((kt + 1) * TK + srow) * 128 + sc0;
            const uint32_t d = sb + SM_STG((kt + 1 - kt0) & 1);
            cpasync16(d + OFF_K + SWZ(srow * 128 + sc0),      ks);
            cpasync16(d + OFF_K + SWZ(srow * 128 + sc0 + 16), ks + 16);
            cpasync16(d + OFF_V + SWZ(srow * 128 + sc0),      vs);
            cpasync16(d + OFF_V + SWZ(srow * 128 + sc0 + 16), vs + 16);
            asm volatile("cp.async.commit_group;" ::: "memory");
        }

        // per-warp window skip (uniform across warp)
        const int jb = kt * TK;
        if (jb > qmax || jb + (TK - 1) < qmin - (WINDOW - 1)) continue;
        const bool fullv = (jb + (TK - 1) <= qmin) && (jb >= qmax - (WINDOW - 1));

        const uint32_t sk = sb + SM_STG((kt - kt0) & 1) + OFF_K;
        const uint32_t sv = sb + SM_STG((kt - kt0) & 1) + OFF_V;
        const int qr0 = qmin + g_;
        const int qr1 = qr0 + 8;

        // ---- two n32-halves; each: QK -> softmax -> PV (P stays in registers) ----
        #pragma unroll
        for (int h = 0; h < 2; h++) {
            float s[4][4];
            #pragma unroll
            for (int i = 0; i < 4; i++)
                #pragma unroll
                for (int e = 0; e < 4; e++) s[i][e] = 0.0f;

            #pragma unroll
            for (int kc = 0; kc < 4; kc++) {
                uint32_t kb0[4], kb1[4];
                ldsm4(kb0, sk + SWZ(((2 * h)     * 16 + rkK) * 128 + kc * 32 + cK16));
                ldsm4(kb1, sk + SWZ(((2 * h + 1) * 16 + rkK) * 128 + kc * 32 + cK16));
                mma16816(s[0], aq[kc], kb0[0], kb0[1]);
                mma16816(s[1], aq[kc], kb0[2], kb0[3]);
                mma16816(s[2], aq[kc], kb1[0], kb1[1]);
                mma16816(s[3], aq[kc], kb1[2], kb1[3]);
            }

            // ---- softmax numerator + pack into PV A-fragments (single fp16) ----
            uint32_t pa[2][4];
            #pragma unroll
            for (int ln = 0; ln < 4; ln++) {
                const int nb = 4 * h + ln;
                float p0, p1, p2, p3;
                if (fullv) {
                    p0 = ex2f_(s[ln][0]);
                    p1 = ex2f_(s[ln][1]);
                    p2 = ex2f_(s[ln][2]);
                    p3 = ex2f_(s[ln][3]);
                } else {
                    const int j0 = jb + nb * 8 + 2 * tig;
                    const int j1 = j0 + 1;
                    p0 = (j0 <= qr0 && j0 + (WINDOW - 1) >= qr0) ? ex2f_(s[ln][0]) : 0.0f;
                    p1 = (j1 <= qr0 && j1 + (WINDOW - 1) >= qr0) ? ex2f_(s[ln][1]) : 0.0f;
                    p2 = (j0 <= qr1 && j0 + (WINDOW - 1) >= qr1) ? ex2f_(s[ln][2]) : 0.0f;
                    p3 = (j1 <= qr1 && j1 + (WINDOW - 1) >= qr1) ? ex2f_(s[ln][3]) : 0.0f;
                }
                l0 += p0 + p1;
                l1 += p2 + p3;
                const int c = ln >> 1, sub = ln & 1;
                pa[c][sub * 2]     = pack2h(p0, p1);
                pa[c][sub * 2 + 1] = pack2h(p2, p3);
            }

            // ---- PV for this half's two key chunks ----
            #pragma unroll
            for (int c = 0; c < 2; c++) {
                const int kc2 = 2 * h + c;
                #pragma unroll
                for (int pr = 0; pr < 4; pr++) {
                    uint32_t vb[4];
                    ldsm4t(vb, sv + SWZ((kc2 * 16 + rkV) * 128 + pr * 32 + cV16));
                    mma16816(o[2 * pr],     pa[c], vb[0], vb[1]);
                    mma16816(o[2 * pr + 1], pa[c], vb[2], vb[3]);
                }
            }
        }
    }

    // ---- finalize ----
    l0 += __shfl_xor_sync(0xffffffffu, l0, 1);
    l0 += __shfl_xor_sync(0xffffffffu, l0, 2);
    l1 += __shfl_xor_sync(0xffffffffu, l1, 1);
    l1 += __shfl_xor_sync(0xffffffffu, l1, 2);
    const float inv0 = 1.0f / l0;
    const float inv1 = 1.0f / l1;

    const int r0 = q0 + (warp << 4) + g_;
    const int r1 = r0 + 8;
    float* orow0 = Op + base + (size_t)r0 * DD;
    float* orow1 = Op + base + (size_t)r1 * DD;
    #pragma unroll
    for (int nb = 0; nb < 8; nb++) {
        const int c = nb * 8 + 2 * tig;
        *(float2*)(orow0 + c) = make_float2(o[nb][0] * inv0, o[nb][1] * inv0);
        *(float2*)(orow1 + c) = make_float2(o[nb][2] * inv1, o[nb][3] * inv1);
    }
}

extern "C" void kernel_launch(void* const* d_in, const int* in_sizes, int n_in,
                              void* d_out, int out_size) {
    const float* Q = (const float*)d_in[0];
    const float* K = (const float*)d_in[1];
    const float* V = (const float*)d_in[2];
    float* O = (float*)d_out;
    (void)in_sizes; (void)n_in; (void)out_size;

    cvt_kv_kernel<<<(KV_CHUNKS + 511) / 512, 512>>>(K, V);

    cudaFuncSetAttribute(swa_mma_kernel, cudaFuncAttributeMaxDynamicSharedMemorySize, SM_TOTAL);
    dim3 grid(S_LEN / TQ, BH);   // (32, 16) = 512 blocks
    swa_mma_kernel<<<grid, NTH, SM_TOTAL>>>(Q, O);
}